// round 6
// baseline (speedup 1.0000x reference)
#include <cuda_runtime.h>
#include <cuda_fp16.h>

#define N_B 32
#define N_N 2048
#define N_D 16
#define N_C 64
#define N_E 32
#define NPART 37
#define SBCE (N_B * N_C * N_E)   // 65536

typedef unsigned long long ull;

// Scratch (device globals; allocation-free kernel_launch)
__device__ __half g_u[(size_t)N_B * N_N * N_C * N_E];        // 256 MB fp16 predictions
__device__ float  g_partials[(size_t)NPART * SBCE];          // partial s sums
__device__ float  g_vsum[SBCE];                              // sum of v_j so far

// ---- packed f32x2 helpers (sm_100+) ----
__device__ __forceinline__ ull ffma2(ull a, ull b, ull c) {
    ull d;
    asm("fma.rn.f32x2 %0, %1, %2, %3;" : "=l"(d) : "l"(a), "l"(b), "l"(c));
    return d;
}
__device__ __forceinline__ ull fadd2(ull a, ull b) {
    ull d;
    asm("add.rn.f32x2 %0, %1, %2;" : "=l"(d) : "l"(a), "l"(b));
    return d;
}
__device__ __forceinline__ ull fpack2(float lo, float hi) {
    ull d;
    asm("mov.b64 %0, {%1, %2};" : "=l"(d) : "f"(lo), "f"(hi));
    return d;
}
__device__ __forceinline__ float2 funpack2(ull v) {
    float2 f;
    asm("mov.b64 {%0, %1}, %2;" : "=f"(f.x), "=f"(f.y) : "l"(v));
    return f;
}

// ---- cp.async helpers ----
__device__ __forceinline__ void cp16(void* smem_dst, const void* gmem_src) {
    unsigned s = (unsigned)__cvta_generic_to_shared(smem_dst);
    asm volatile("cp.async.cg.shared.global [%0], [%1], 16;" :: "r"(s), "l"(gmem_src));
}
__device__ __forceinline__ void cp_commit() {
    asm volatile("cp.async.commit_group;");
}
__device__ __forceinline__ void cp_wait2() {
    asm volatile("cp.async.wait_group 2;" ::: "memory");
}
__device__ __forceinline__ void cp_wait3() {
    asm volatile("cp.async.wait_group 3;" ::: "memory");
}

// capsA dynamic smem layout: Ws[3][4096] floats, then xs[3][512] floats
#define CAPSA_WS_FLOATS (3 * 4096)
#define CAPSA_XS_FLOATS (3 * 512)
#define CAPSA_SMEM_BYTES ((CAPSA_WS_FLOATS + CAPSA_XS_FLOATS) * 4)

// ---------------------------------------------------------------------------
// Kernel A: u = x*W + B via packed f32x2 FFMA, store u fp16, accumulate sum_n u
// (unchanged from passing round-5 version)
// ---------------------------------------------------------------------------
__global__ __launch_bounds__(256, 2)
void capsA(const float* __restrict__ x, const float* __restrict__ W,
           const float* __restrict__ Bv)
{
    extern __shared__ float smem[];
    float* Wsm = smem;                        // [3][4096]
    float* xsm = smem + CAPSA_WS_FLOATS;      // [3][512]

    const int tid = threadIdx.x;
    const int cc  = blockIdx.x;            // c-chunk 0..7
    const int nb  = blockIdx.y;            // n-block 0..36
    const int c0  = cc * 8;
    const int ns  = (nb * N_N) / NPART;
    const int ne  = ((nb + 1) * N_N) / NPART;

    const int lane    = tid & 31;
    const int bq      = tid >> 5;          // 0..7 (b group of 4)
    const int c_local = lane >> 2;         // 0..7
    const int a       = lane & 3;          // e-octet selector: e base = 8*a
    const int swz4    = c_local & 7;
    const int c       = c0 + c_local;
    const int e_base  = 8 * a;

    ull Bv2[4];
    #pragma unroll
    for (int j = 0; j < 4; j++)
        Bv2[j] = fpack2(Bv[c * N_E + e_base + 2 * j],
                        Bv[c * N_E + e_base + 2 * j + 1]);

    ull sacc[4][4];
    #pragma unroll
    for (int i = 0; i < 4; i++)
        #pragma unroll
        for (int j = 0; j < 4; j++) sacc[i][j] = 0ull;

    auto stage = [&](int n, int buf) {
        const float* Wn = W + (size_t)n * (N_C * N_D * N_E) + (size_t)c0 * (N_D * N_E);
        float* Wb = Wsm + buf * 4096;
        #pragma unroll
        for (int k = 0; k < 4; k++) {
            int q = tid + 256 * k;         // float4 index 0..1023
            int p = q * 4;
            int cl = p >> 9;
            int d  = (p >> 5) & 15;
            int e4 = (p & 31) >> 2;
            float* dst = &Wb[cl * 512 + d * 32 + ((e4 ^ (cl & 7)) << 2)];
            cp16(dst, Wn + p);
        }
        if (tid < 128) {
            int b = tid >> 2, dq = tid & 3;
            cp16(&xsm[buf * 512 + b * N_D + dq * 4],
                 x + ((size_t)b * N_N + n) * N_D + dq * 4);
        }
        cp_commit();
    };

    stage(ns, 0);
    if (ns + 1 < ne) stage(ns + 1, 1); else cp_commit();

    int buf = 0;
    for (int n = ns; n < ne; n++) {
        int nxt = n + 2;
        if (nxt < ne) stage(nxt, (nxt - ns) % 3); else cp_commit();
        cp_wait2();
        __syncthreads();

        ull uacc[4][4];
        #pragma unroll
        for (int i = 0; i < 4; i++)
            #pragma unroll
            for (int j = 0; j < 4; j++) uacc[i][j] = 0ull;

        const float* Wrow = Wsm + buf * 4096 + c_local * 512;
        const float* xrow = xsm + buf * 512;
        #pragma unroll
        for (int d = 0; d < N_D; d++) {
            ull xv[4];
            #pragma unroll
            for (int i = 0; i < 4; i++) {
                float xval = xrow[(bq * 4 + i) * N_D + d];
                xv[i] = fpack2(xval, xval);
            }
            int o0 = (((2 * a + 0) ^ swz4) << 2) + d * 32;
            int o1 = (((2 * a + 1) ^ swz4) << 2) + d * 32;
            ulonglong2 w01 = *reinterpret_cast<const ulonglong2*>(Wrow + o0);
            ulonglong2 w23 = *reinterpret_cast<const ulonglong2*>(Wrow + o1);
            ull wv[4] = { w01.x, w01.y, w23.x, w23.y };
            #pragma unroll
            for (int i = 0; i < 4; i++)
                #pragma unroll
                for (int j = 0; j < 4; j++)
                    uacc[i][j] = ffma2(xv[i], wv[j], uacc[i][j]);
        }

        #pragma unroll
        for (int i = 0; i < 4; i++) {
            int b = bq * 4 + i;
            unsigned h[4];
            #pragma unroll
            for (int j = 0; j < 4; j++) {
                ull t = fadd2(uacc[i][j], Bv2[j]);
                sacc[i][j] = fadd2(sacc[i][j], t);
                float2 tf = funpack2(t);
                __half2 hh = __floats2half2_rn(tf.x, tf.y);
                h[j] = reinterpret_cast<unsigned&>(hh);
            }
            size_t uoff = (((size_t)b * N_N + n) * N_C + c) * N_E + e_base;
            *reinterpret_cast<uint4*>(&g_u[uoff]) = make_uint4(h[0], h[1], h[2], h[3]);
        }
        __syncthreads();
        buf = (buf == 2) ? 0 : buf + 1;
    }

    #pragma unroll
    for (int i = 0; i < 4; i++) {
        int b = bq * 4 + i;
        ull* dst = reinterpret_cast<ull*>(
            &g_partials[(size_t)nb * SBCE + ((size_t)b * N_C + c) * N_E + e_base]);
        *reinterpret_cast<ulonglong2*>(dst)     = make_ulonglong2(sacc[i][0], sacc[i][1]);
        *reinterpret_cast<ulonglong2*>(dst + 2) = make_ulonglong2(sacc[i][2], sacc[i][3]);
    }
}

// ---------------------------------------------------------------------------
// Kernel B: routing pass.  logits = u . vsum, coup = softmax_c, s += coup*u
// grid (32 b, 37 n-blocks), 256 threads.  One capsule c per thread, lane-quads.
// Ring of 4 u-tiles, prefetch distance 3 (wait_group 3) to hide DRAM latency.
// ---------------------------------------------------------------------------
__global__ __launch_bounds__(256, 8)
void capsB()
{
    __shared__ __half us[4][N_C * N_E];   // 4-deep ring of u tiles (4 x 4KB)
    __shared__ float  wsum[2][8];

    const int tid  = threadIdx.x;
    const int b    = blockIdx.x;
    const int nb   = blockIdx.y;
    const int ns   = (nb * N_N) / NPART;
    const int ne   = ((nb + 1) * N_N) / NPART;
    const int q    = tid & 3;      // e-octet within c
    const int c    = tid >> 2;     // 0..63
    const int lane = tid & 31;
    const int wid  = tid >> 5;

    float vs[8];
    {
        const float4* vp = reinterpret_cast<const float4*>(
            g_vsum + ((size_t)b * N_C + c) * N_E + q * 8);
        float4 v0 = vp[0], v1 = vp[1];
        vs[0] = v0.x; vs[1] = v0.y; vs[2] = v0.z; vs[3] = v0.w;
        vs[4] = v1.x; vs[5] = v1.y; vs[6] = v1.z; vs[7] = v1.w;
    }
    float sacc[8];
    #pragma unroll
    for (int i = 0; i < 8; i++) sacc[i] = 0.0f;

    const size_t ubase = (size_t)b * N_N * (N_C * N_E);

    auto stage = [&](int n, int buf) {
        cp16(&us[buf][tid * 8], &g_u[ubase + (size_t)n * (N_C * N_E) + tid * 8]);
        cp_commit();
    };

    // prologue: 3 tiles in flight
    stage(ns, 0);
    if (ns + 1 < ne) stage(ns + 1, 1); else cp_commit();
    if (ns + 2 < ne) stage(ns + 2, 2); else cp_commit();

    for (int n = ns; n < ne; n++) {
        int r   = n - ns;
        int cur = r & 3;
        int nxt = n + 3;
        if (nxt < ne) stage(nxt, (r + 3) & 3); else cp_commit();
        cp_wait3();        // tile for n retired (groups complete in order)
        __syncthreads();   // tile visible to all; wsum[r&1] free

        uint4 raw = *reinterpret_cast<const uint4*>(&us[cur][tid * 8]);
        float2 f0 = __half22float2(reinterpret_cast<__half2&>(raw.x));
        float2 f1 = __half22float2(reinterpret_cast<__half2&>(raw.y));
        float2 f2 = __half22float2(reinterpret_cast<__half2&>(raw.z));
        float2 f3 = __half22float2(reinterpret_cast<__half2&>(raw.w));

        float lp = f0.x * vs[0];
        lp = fmaf(f0.y, vs[1], lp);
        lp = fmaf(f1.x, vs[2], lp);
        lp = fmaf(f1.y, vs[3], lp);
        lp = fmaf(f2.x, vs[4], lp);
        lp = fmaf(f2.y, vs[5], lp);
        lp = fmaf(f3.x, vs[6], lp);
        lp = fmaf(f3.y, vs[7], lp);
        lp += __shfl_xor_sync(0xffffffffu, lp, 1);
        lp += __shfl_xor_sync(0xffffffffu, lp, 2);

        float ex = __expf(lp);
        float s = ex;
        #pragma unroll
        for (int m = 16; m >= 1; m >>= 1)
            s += __shfl_xor_sync(0xffffffffu, s, m);
        if (lane == 0) wsum[r & 1][wid] = s;
        __syncthreads();
        float tot = 0.0f;
        #pragma unroll
        for (int w = 0; w < 8; w++) tot += wsum[r & 1][w];
        float coup = 4.0f * ex / tot;   // tot counts each c 4x (quad replication)

        sacc[0] = fmaf(coup, f0.x, sacc[0]);
        sacc[1] = fmaf(coup, f0.y, sacc[1]);
        sacc[2] = fmaf(coup, f1.x, sacc[2]);
        sacc[3] = fmaf(coup, f1.y, sacc[3]);
        sacc[4] = fmaf(coup, f2.x, sacc[4]);
        sacc[5] = fmaf(coup, f2.y, sacc[5]);
        sacc[6] = fmaf(coup, f3.x, sacc[6]);
        sacc[7] = fmaf(coup, f3.y, sacc[7]);
    }

    float* dst = &g_partials[(size_t)nb * SBCE + ((size_t)b * N_C + c) * N_E + q * 8];
    *reinterpret_cast<float4*>(dst)     = make_float4(sacc[0], sacc[1], sacc[2], sacc[3]);
    *reinterpret_cast<float4*>(dst + 4) = make_float4(sacc[4], sacc[5], sacc[6], sacc[7]);
}

// ---------------------------------------------------------------------------
// reduce partials (fixed order -> deterministic) + squash; update vsum
// 64 blocks x 256 threads; thread = (bc, e-quad); 37 independent LDG.128.
// ---------------------------------------------------------------------------
__global__ __launch_bounds__(256, 8)
void reduce_squash(float scale, int overwrite, float* __restrict__ out)
{
    int gt = blockIdx.x * 256 + threadIdx.x;   // 0..16383
    int bc = gt >> 3;                          // b*64 + c
    int e4 = (gt & 7) * 4;                     // e quad base
    size_t idx = (size_t)bc * N_E + e4;

    float4 s = make_float4(0.f, 0.f, 0.f, 0.f);
    #pragma unroll
    for (int p = 0; p < NPART; p++) {
        float4 v = *reinterpret_cast<const float4*>(&g_partials[(size_t)p * SBCE + idx]);
        s.x += v.x; s.y += v.y; s.z += v.z; s.w += v.w;
    }
    s.x *= scale; s.y *= scale; s.z *= scale; s.w *= scale;

    float nsq = s.x * s.x + s.y * s.y + s.z * s.z + s.w * s.w;
    // sum over the 8 lanes covering this bc (lanes aligned in groups of 8)
    nsq += __shfl_xor_sync(0xffffffffu, nsq, 1);
    nsq += __shfl_xor_sync(0xffffffffu, nsq, 2);
    nsq += __shfl_xor_sync(0xffffffffu, nsq, 4);

    float sc = nsq / ((1.0f + nsq) * sqrtf(nsq + 1e-9f));
    float4 v = make_float4(sc * s.x, sc * s.y, sc * s.z, sc * s.w);

    float4* vp = reinterpret_cast<float4*>(&g_vsum[idx]);
    if (overwrite) {
        *vp = v;
    } else {
        float4 old = *vp;
        *vp = make_float4(old.x + v.x, old.y + v.y, old.z + v.z, old.w + v.w);
    }
    if (out) *reinterpret_cast<float4*>(out + idx) = v;
}

// ---------------------------------------------------------------------------
extern "C" void kernel_launch(void* const* d_in, const int* in_sizes, int n_in,
                              void* d_out, int out_size)
{
    const float* x  = (const float*)d_in[0];
    const float* W  = (const float*)d_in[1];
    const float* Bv = (const float*)d_in[2];
    float* out = (float*)d_out;

    cudaFuncSetAttribute(capsA, cudaFuncAttributeMaxDynamicSharedMemorySize,
                         CAPSA_SMEM_BYTES);

    dim3 gA(8, NPART);
    dim3 gB(N_B, NPART);

    capsA<<<gA, 256, CAPSA_SMEM_BYTES>>>(x, W, Bv);
    reduce_squash<<<64, 256>>>(1.0f / 64.0f, 1, nullptr);   // v1 -> vsum
    capsB<<<gB, 256>>>();
    reduce_squash<<<64, 256>>>(1.0f, 0, nullptr);           // vsum += v2
    capsB<<<gB, 256>>>();
    reduce_squash<<<64, 256>>>(1.0f, 0, out);
}

// round 8
// speedup vs baseline: 1.0510x; 1.0510x over previous
#include <cuda_runtime.h>
#include <cuda_fp16.h>

#define N_B 32
#define N_N 2048
#define N_D 16
#define N_C 64
#define N_E 32
#define NPART 37
#define SBCE (N_B * N_C * N_E)   // 65536

typedef unsigned long long ull;

// Scratch (device globals; allocation-free kernel_launch)
__device__ __half g_u[(size_t)N_B * N_N * N_C * N_E];        // 256 MB fp16 predictions
__device__ float  g_partials[(size_t)NPART * SBCE];          // partial s sums
__device__ float  g_vsum[SBCE];                              // sum of v_j so far

// ---- packed f32x2 helpers (sm_100+) ----
__device__ __forceinline__ ull ffma2(ull a, ull b, ull c) {
    ull d;
    asm("fma.rn.f32x2 %0, %1, %2, %3;" : "=l"(d) : "l"(a), "l"(b), "l"(c));
    return d;
}
__device__ __forceinline__ ull fadd2(ull a, ull b) {
    ull d;
    asm("add.rn.f32x2 %0, %1, %2;" : "=l"(d) : "l"(a), "l"(b));
    return d;
}
__device__ __forceinline__ ull fpack2(float lo, float hi) {
    ull d;
    asm("mov.b64 %0, {%1, %2};" : "=l"(d) : "f"(lo), "f"(hi));
    return d;
}
__device__ __forceinline__ float2 funpack2(ull v) {
    float2 f;
    asm("mov.b64 {%0, %1}, %2;" : "=f"(f.x), "=f"(f.y) : "l"(v));
    return f;
}

// ---- cp.async helpers ----
__device__ __forceinline__ void cp16(void* smem_dst, const void* gmem_src) {
    unsigned s = (unsigned)__cvta_generic_to_shared(smem_dst);
    asm volatile("cp.async.cg.shared.global [%0], [%1], 16;" :: "r"(s), "l"(gmem_src));
}
__device__ __forceinline__ void cp_commit() {
    asm volatile("cp.async.commit_group;");
}
__device__ __forceinline__ void cp_wait1() {
    asm volatile("cp.async.wait_group 1;" ::: "memory");
}
__device__ __forceinline__ void cp_wait3() {
    asm volatile("cp.async.wait_group 3;" ::: "memory");
}

// capsA dynamic smem: 4-deep ring.  Ws[4][4096] floats + xs[4][512] floats
#define CAPSA_WS_FLOATS (4 * 4096)
#define CAPSA_XS_FLOATS (4 * 512)
#define CAPSA_SMEM_BYTES ((CAPSA_WS_FLOATS + CAPSA_XS_FLOATS) * 4)

__global__ void dumk() {}   // 1 pad launch: aligns ncu -s 5 onto capsB pass 3

// ---------------------------------------------------------------------------
// Kernel A: u = x*W + B via packed f32x2 FFMA, store u fp16, accumulate sum_n u
// grid (8 c-chunks, 37 n-blocks) = 296 blocks (2/SM), 256 threads.
// Thread tile: 4 b x 1 c x 4 e-pairs.  4-stage cp.async pipeline (depth 3).
// ---------------------------------------------------------------------------
__global__ __launch_bounds__(256, 2)
void capsA(const float* __restrict__ x, const float* __restrict__ W,
           const float* __restrict__ Bv)
{
    extern __shared__ float smem[];
    float* Wsm = smem;                        // [4][4096]
    float* xsm = smem + CAPSA_WS_FLOATS;      // [4][512]

    const int tid = threadIdx.x;
    const int cc  = blockIdx.x;            // c-chunk 0..7
    const int nb  = blockIdx.y;            // n-block 0..36
    const int c0  = cc * 8;
    const int ns  = (nb * N_N) / NPART;
    const int ne  = ((nb + 1) * N_N) / NPART;

    const int lane    = tid & 31;
    const int bq      = tid >> 5;          // 0..7 (b group of 4)
    const int c_local = lane >> 2;         // 0..7
    const int a       = lane & 3;          // e-octet selector: e base = 8*a
    const int swz4    = c_local & 7;
    const int c       = c0 + c_local;
    const int e_base  = 8 * a;

    ull Bv2[4];
    #pragma unroll
    for (int j = 0; j < 4; j++)
        Bv2[j] = fpack2(Bv[c * N_E + e_base + 2 * j],
                        Bv[c * N_E + e_base + 2 * j + 1]);

    ull sacc[4][4];
    #pragma unroll
    for (int i = 0; i < 4; i++)
        #pragma unroll
        for (int j = 0; j < 4; j++) sacc[i][j] = 0ull;

    auto stage = [&](int n, int buf) {
        const float* Wn = W + (size_t)n * (N_C * N_D * N_E) + (size_t)c0 * (N_D * N_E);
        float* Wb = Wsm + buf * 4096;
        #pragma unroll
        for (int k = 0; k < 4; k++) {
            int q = tid + 256 * k;         // float4 index 0..1023
            int p = q * 4;
            int cl = p >> 9;
            int d  = (p >> 5) & 15;
            int e4 = (p & 31) >> 2;
            float* dst = &Wb[cl * 512 + d * 32 + ((e4 ^ (cl & 7)) << 2)];
            cp16(dst, Wn + p);
        }
        if (tid < 128) {
            int b = tid >> 2, dq = tid & 3;
            cp16(&xsm[buf * 512 + b * N_D + dq * 4],
                 x + ((size_t)b * N_N + n) * N_D + dq * 4);
        }
        cp_commit();
    };

    // prologue: three stages in flight (relative buffer indexing)
    stage(ns, 0);
    if (ns + 1 < ne) stage(ns + 1, 1); else cp_commit();
    if (ns + 2 < ne) stage(ns + 2, 2); else cp_commit();

    for (int n = ns; n < ne; n++) {
        int r   = n - ns;
        int buf = r & 3;
        int nxt = n + 3;
        if (nxt < ne) stage(nxt, (r + 3) & 3); else cp_commit();
        cp_wait3();                        // group for n retired
        __syncthreads();                   // data for n visible to all

        ull uacc[4][4];
        #pragma unroll
        for (int i = 0; i < 4; i++)
            #pragma unroll
            for (int j = 0; j < 4; j++) uacc[i][j] = 0ull;

        const float* Wrow = Wsm + buf * 4096 + c_local * 512;
        const float* xrow = xsm + buf * 512;
        #pragma unroll
        for (int d = 0; d < N_D; d++) {
            ull xv[4];
            #pragma unroll
            for (int i = 0; i < 4; i++) {
                float xval = xrow[(bq * 4 + i) * N_D + d];
                xv[i] = fpack2(xval, xval);
            }
            int o0 = (((2 * a + 0) ^ swz4) << 2) + d * 32;
            int o1 = (((2 * a + 1) ^ swz4) << 2) + d * 32;
            ulonglong2 w01 = *reinterpret_cast<const ulonglong2*>(Wrow + o0);
            ulonglong2 w23 = *reinterpret_cast<const ulonglong2*>(Wrow + o1);
            ull wv[4] = { w01.x, w01.y, w23.x, w23.y };
            #pragma unroll
            for (int i = 0; i < 4; i++)
                #pragma unroll
                for (int j = 0; j < 4; j++)
                    uacc[i][j] = ffma2(xv[i], wv[j], uacc[i][j]);
        }

        // epilogue: +B, accumulate s1 partial, convert+store fp16 u
        #pragma unroll
        for (int i = 0; i < 4; i++) {
            int b = bq * 4 + i;
            unsigned h[4];
            #pragma unroll
            for (int j = 0; j < 4; j++) {
                ull t = fadd2(uacc[i][j], Bv2[j]);
                sacc[i][j] = fadd2(sacc[i][j], t);
                float2 tf = funpack2(t);
                __half2 hh = __floats2half2_rn(tf.x, tf.y);
                h[j] = reinterpret_cast<unsigned&>(hh);
            }
            size_t uoff = (((size_t)b * N_N + n) * N_C + c) * N_E + e_base;
            *reinterpret_cast<uint4*>(&g_u[uoff]) = make_uint4(h[0], h[1], h[2], h[3]);
        }
        __syncthreads();                   // buf may be restaged next iter
    }

    // write partial sums
    #pragma unroll
    for (int i = 0; i < 4; i++) {
        int b = bq * 4 + i;
        ull* dst = reinterpret_cast<ull*>(
            &g_partials[(size_t)nb * SBCE + ((size_t)b * N_C + c) * N_E + e_base]);
        *reinterpret_cast<ulonglong2*>(dst)     = make_ulonglong2(sacc[i][0], sacc[i][1]);
        *reinterpret_cast<ulonglong2*>(dst + 2) = make_ulonglong2(sacc[i][2], sacc[i][3]);
    }
}

// ---------------------------------------------------------------------------
// Kernel B (round-5 proven version): logits = u.vsum, softmax_c, s += coup*u
// grid (32 b, 37 n-blocks), 256 threads.  One capsule per thread, lane-quads.
// Double-buffered cp.async (wait1): 8 blocks/SM keep aggregate MLP high.
// ---------------------------------------------------------------------------
__global__ __launch_bounds__(256, 8)
void capsB()
{
    __shared__ __half us[2][N_C * N_E];   // double-buffered u tile (2 x 4KB)
    __shared__ float  wsum[2][8];

    const int tid  = threadIdx.x;
    const int b    = blockIdx.x;
    const int nb   = blockIdx.y;
    const int ns   = (nb * N_N) / NPART;
    const int ne   = ((nb + 1) * N_N) / NPART;
    const int q    = tid & 3;      // e-octet within c
    const int c    = tid >> 2;     // 0..63
    const int lane = tid & 31;
    const int wid  = tid >> 5;

    float vs[8];
    {
        const float4* vp = reinterpret_cast<const float4*>(
            g_vsum + ((size_t)b * N_C + c) * N_E + q * 8);
        float4 v0 = vp[0], v1 = vp[1];
        vs[0] = v0.x; vs[1] = v0.y; vs[2] = v0.z; vs[3] = v0.w;
        vs[4] = v1.x; vs[5] = v1.y; vs[6] = v1.z; vs[7] = v1.w;
    }
    float sacc[8];
    #pragma unroll
    for (int i = 0; i < 8; i++) sacc[i] = 0.0f;

    {
        size_t base = ((size_t)b * N_N + ns) * (N_C * N_E);
        cp16(&us[0][tid * 8], &g_u[base + tid * 8]);
        cp_commit();
    }

    for (int n = ns; n < ne; n++) {
        int cur = (n - ns) & 1;
        if (n + 1 < ne) {
            size_t base = ((size_t)b * N_N + (n + 1)) * (N_C * N_E);
            cp16(&us[cur ^ 1][tid * 8], &g_u[base + tid * 8]);
        }
        cp_commit();
        cp_wait1();
        __syncthreads();   // us[cur] ready, wsum[cur] free

        uint4 raw = *reinterpret_cast<const uint4*>(&us[cur][tid * 8]);
        float2 f0 = __half22float2(reinterpret_cast<__half2&>(raw.x));
        float2 f1 = __half22float2(reinterpret_cast<__half2&>(raw.y));
        float2 f2 = __half22float2(reinterpret_cast<__half2&>(raw.z));
        float2 f3 = __half22float2(reinterpret_cast<__half2&>(raw.w));

        float lp = f0.x * vs[0];
        lp = fmaf(f0.y, vs[1], lp);
        lp = fmaf(f1.x, vs[2], lp);
        lp = fmaf(f1.y, vs[3], lp);
        lp = fmaf(f2.x, vs[4], lp);
        lp = fmaf(f2.y, vs[5], lp);
        lp = fmaf(f3.x, vs[6], lp);
        lp = fmaf(f3.y, vs[7], lp);
        lp += __shfl_xor_sync(0xffffffffu, lp, 1);
        lp += __shfl_xor_sync(0xffffffffu, lp, 2);

        float ex = __expf(lp);
        float s = ex;
        #pragma unroll
        for (int m = 16; m >= 1; m >>= 1)
            s += __shfl_xor_sync(0xffffffffu, s, m);
        if (lane == 0) wsum[cur][wid] = s;
        __syncthreads();
        float tot = 0.0f;
        #pragma unroll
        for (int w = 0; w < 8; w++) tot += wsum[cur][w];
        float coup = 4.0f * ex / tot;   // tot counts each c 4x (quad replication)

        sacc[0] = fmaf(coup, f0.x, sacc[0]);
        sacc[1] = fmaf(coup, f0.y, sacc[1]);
        sacc[2] = fmaf(coup, f1.x, sacc[2]);
        sacc[3] = fmaf(coup, f1.y, sacc[3]);
        sacc[4] = fmaf(coup, f2.x, sacc[4]);
        sacc[5] = fmaf(coup, f2.y, sacc[5]);
        sacc[6] = fmaf(coup, f3.x, sacc[6]);
        sacc[7] = fmaf(coup, f3.y, sacc[7]);
    }

    float* dst = &g_partials[(size_t)nb * SBCE + ((size_t)b * N_C + c) * N_E + q * 8];
    *reinterpret_cast<float4*>(dst)     = make_float4(sacc[0], sacc[1], sacc[2], sacc[3]);
    *reinterpret_cast<float4*>(dst + 4) = make_float4(sacc[4], sacc[5], sacc[6], sacc[7]);
}

// ---------------------------------------------------------------------------
// reduce partials (round-5 proven version): 2048 blocks x 32 threads
// ---------------------------------------------------------------------------
__global__ void reduce_squash(float scale, int overwrite, float* __restrict__ out)
{
    int bc = blockIdx.x;     // b*64 + c
    int e  = threadIdx.x;
    size_t idx = (size_t)bc * N_E + e;
    float s = 0.0f;
    #pragma unroll
    for (int p = 0; p < NPART; p++)
        s += g_partials[(size_t)p * SBCE + idx];
    s *= scale;
    float nsq = s * s;
    #pragma unroll
    for (int m = 16; m >= 1; m >>= 1)
        nsq += __shfl_xor_sync(0xffffffffu, nsq, m);
    float sc = nsq / ((1.0f + nsq) * sqrtf(nsq + 1e-9f));
    float v = sc * s;
    if (overwrite) g_vsum[idx] = v;
    else           g_vsum[idx] += v;
    if (out) out[idx] = v;
}

// ---------------------------------------------------------------------------
extern "C" void kernel_launch(void* const* d_in, const int* in_sizes, int n_in,
                              void* d_out, int out_size)
{
    const float* x  = (const float*)d_in[0];
    const float* W  = (const float*)d_in[1];
    const float* Bv = (const float*)d_in[2];
    float* out = (float*)d_out;

    cudaFuncSetAttribute(capsA, cudaFuncAttributeMaxDynamicSharedMemorySize,
                         CAPSA_SMEM_BYTES);

    dim3 gA(8, NPART);
    dim3 gB(N_B, NPART);

    dumk<<<1, 32>>>();   // shifts ncu -s 5 capture onto capsB (pass 3)

    capsA<<<gA, 256, CAPSA_SMEM_BYTES>>>(x, W, Bv);
    reduce_squash<<<N_B * N_C, 32>>>(1.0f / 64.0f, 1, nullptr);   // v1 -> vsum
    capsB<<<gB, 256>>>();
    reduce_squash<<<N_B * N_C, 32>>>(1.0f, 0, nullptr);           // vsum += v2
    capsB<<<gB, 256>>>();
    reduce_squash<<<N_B * N_C, 32>>>(1.0f, 0, out);
}

// round 13
// speedup vs baseline: 1.1519x; 1.0960x over previous
// CapsuleLayer r12 — fixes uint4 row-stride bug in capsB (128 -> 256)
#include <cuda_runtime.h>
#include <cuda_fp16.h>

#define N_B 32
#define N_N 2048
#define N_D 16
#define N_C 64
#define N_E 32
#define NPART 37
#define SBCE (N_B * N_C * N_E)   // 65536
#define U_ROW_U4 ((N_C * N_E) / 8)   // one n-row of u in uint4 units = 256

typedef unsigned long long ull;

// Scratch (device globals; allocation-free kernel_launch)
__device__ __half g_u[(size_t)N_B * N_N * N_C * N_E];        // 256 MB fp16 predictions
__device__ float  g_partials[(size_t)NPART * SBCE];          // partial s sums
__device__ float  g_vsum[SBCE];                              // sum of v_j so far

// ---- packed f32x2 helpers (sm_100+) ----
__device__ __forceinline__ ull ffma2(ull a, ull b, ull c) {
    ull d;
    asm("fma.rn.f32x2 %0, %1, %2, %3;" : "=l"(d) : "l"(a), "l"(b), "l"(c));
    return d;
}
__device__ __forceinline__ ull fadd2(ull a, ull b) {
    ull d;
    asm("add.rn.f32x2 %0, %1, %2;" : "=l"(d) : "l"(a), "l"(b));
    return d;
}
__device__ __forceinline__ ull fpack2(float lo, float hi) {
    ull d;
    asm("mov.b64 %0, {%1, %2};" : "=l"(d) : "f"(lo), "f"(hi));
    return d;
}
__device__ __forceinline__ float2 funpack2(ull v) {
    float2 f;
    asm("mov.b64 {%0, %1}, %2;" : "=f"(f.x), "=f"(f.y) : "l"(v));
    return f;
}
// half2 (as u32) -> packed f32x2 (as ull)
__device__ __forceinline__ ull h2f2(unsigned h) {
    __half2 hh = reinterpret_cast<__half2&>(h);
    float2 f = __half22float2(hh);
    ull r;
    asm("mov.b64 %0, {%1, %2};" : "=l"(r) : "f"(f.x), "f"(f.y));
    return r;
}

// ---- cp.async helpers (capsA only) ----
__device__ __forceinline__ void cp16(void* smem_dst, const void* gmem_src) {
    unsigned s = (unsigned)__cvta_generic_to_shared(smem_dst);
    asm volatile("cp.async.cg.shared.global [%0], [%1], 16;" :: "r"(s), "l"(gmem_src));
}
__device__ __forceinline__ void cp_commit() {
    asm volatile("cp.async.commit_group;");
}
__device__ __forceinline__ void cp_wait3() {
    asm volatile("cp.async.wait_group 3;" ::: "memory");
}

// capsA dynamic smem: 4-deep ring.  Ws[4][4096] floats + xs[4][512] floats
#define CAPSA_WS_FLOATS (4 * 4096)
#define CAPSA_XS_FLOATS (4 * 512)
#define CAPSA_SMEM_BYTES ((CAPSA_WS_FLOATS + CAPSA_XS_FLOATS) * 4)

__global__ void dumk() {}   // 1 pad launch: aligns ncu -s 5 onto capsB pass 3

// ---------------------------------------------------------------------------
// Kernel A (unchanged — measured at its DRAM roofline, ~96us):
// u = x*W + B via packed f32x2 FFMA, store u fp16, accumulate sum_n u
// ---------------------------------------------------------------------------
__global__ __launch_bounds__(256, 2)
void capsA(const float* __restrict__ x, const float* __restrict__ W,
           const float* __restrict__ Bv)
{
    extern __shared__ float smem[];
    float* Wsm = smem;                        // [4][4096]
    float* xsm = smem + CAPSA_WS_FLOATS;      // [4][512]

    const int tid = threadIdx.x;
    const int cc  = blockIdx.x;
    const int nb  = blockIdx.y;
    const int c0  = cc * 8;
    const int ns  = (nb * N_N) / NPART;
    const int ne  = ((nb + 1) * N_N) / NPART;

    const int lane    = tid & 31;
    const int bq      = tid >> 5;
    const int c_local = lane >> 2;
    const int a       = lane & 3;
    const int swz4    = c_local & 7;
    const int c       = c0 + c_local;
    const int e_base  = 8 * a;

    ull Bv2[4];
    #pragma unroll
    for (int j = 0; j < 4; j++)
        Bv2[j] = fpack2(Bv[c * N_E + e_base + 2 * j],
                        Bv[c * N_E + e_base + 2 * j + 1]);

    ull sacc[4][4];
    #pragma unroll
    for (int i = 0; i < 4; i++)
        #pragma unroll
        for (int j = 0; j < 4; j++) sacc[i][j] = 0ull;

    auto stage = [&](int n, int buf) {
        const float* Wn = W + (size_t)n * (N_C * N_D * N_E) + (size_t)c0 * (N_D * N_E);
        float* Wb = Wsm + buf * 4096;
        #pragma unroll
        for (int k = 0; k < 4; k++) {
            int q = tid + 256 * k;
            int p = q * 4;
            int cl = p >> 9;
            int d  = (p >> 5) & 15;
            int e4 = (p & 31) >> 2;
            float* dst = &Wb[cl * 512 + d * 32 + ((e4 ^ (cl & 7)) << 2)];
            cp16(dst, Wn + p);
        }
        if (tid < 128) {
            int b = tid >> 2, dq = tid & 3;
            cp16(&xsm[buf * 512 + b * N_D + dq * 4],
                 x + ((size_t)b * N_N + n) * N_D + dq * 4);
        }
        cp_commit();
    };

    stage(ns, 0);
    if (ns + 1 < ne) stage(ns + 1, 1); else cp_commit();
    if (ns + 2 < ne) stage(ns + 2, 2); else cp_commit();

    for (int n = ns; n < ne; n++) {
        int r   = n - ns;
        int buf = r & 3;
        int nxt = n + 3;
        if (nxt < ne) stage(nxt, (r + 3) & 3); else cp_commit();
        cp_wait3();
        __syncthreads();

        ull uacc[4][4];
        #pragma unroll
        for (int i = 0; i < 4; i++)
            #pragma unroll
            for (int j = 0; j < 4; j++) uacc[i][j] = 0ull;

        const float* Wrow = Wsm + buf * 4096 + c_local * 512;
        const float* xrow = xsm + buf * 512;
        #pragma unroll
        for (int d = 0; d < N_D; d++) {
            ull xv[4];
            #pragma unroll
            for (int i = 0; i < 4; i++) {
                float xval = xrow[(bq * 4 + i) * N_D + d];
                xv[i] = fpack2(xval, xval);
            }
            int o0 = (((2 * a + 0) ^ swz4) << 2) + d * 32;
            int o1 = (((2 * a + 1) ^ swz4) << 2) + d * 32;
            ulonglong2 w01 = *reinterpret_cast<const ulonglong2*>(Wrow + o0);
            ulonglong2 w23 = *reinterpret_cast<const ulonglong2*>(Wrow + o1);
            ull wv[4] = { w01.x, w01.y, w23.x, w23.y };
            #pragma unroll
            for (int i = 0; i < 4; i++)
                #pragma unroll
                for (int j = 0; j < 4; j++)
                    uacc[i][j] = ffma2(xv[i], wv[j], uacc[i][j]);
        }

        #pragma unroll
        for (int i = 0; i < 4; i++) {
            int b = bq * 4 + i;
            unsigned h[4];
            #pragma unroll
            for (int j = 0; j < 4; j++) {
                ull t = fadd2(uacc[i][j], Bv2[j]);
                sacc[i][j] = fadd2(sacc[i][j], t);
                float2 tf = funpack2(t);
                __half2 hh = __floats2half2_rn(tf.x, tf.y);
                h[j] = reinterpret_cast<unsigned&>(hh);
            }
            size_t uoff = (((size_t)b * N_N + n) * N_C + c) * N_E + e_base;
            *reinterpret_cast<uint4*>(&g_u[uoff]) = make_uint4(h[0], h[1], h[2], h[3]);
        }
        __syncthreads();
    }

    #pragma unroll
    for (int i = 0; i < 4; i++) {
        int b = bq * 4 + i;
        ull* dst = reinterpret_cast<ull*>(
            &g_partials[(size_t)nb * SBCE + ((size_t)b * N_C + c) * N_E + e_base]);
        *reinterpret_cast<ulonglong2*>(dst)     = make_ulonglong2(sacc[i][0], sacc[i][1]);
        *reinterpret_cast<ulonglong2*>(dst + 2) = make_ulonglong2(sacc[i][2], sacc[i][3]);
    }
}

// ---------------------------------------------------------------------------
// Kernel B (lean, issue-optimized): logits = u.vsum, softmax_c, s += coup*u.
// Direct LDG.128 with register prefetch distance 2 (no smem staging),
// f32x2 dot/accumulate, 3-shfl exp-sum, 1 barrier per n.
// Thread: c = tid>>2, e-octet q = tid&3; warp covers c in [wid*8, wid*8+8).
// ---------------------------------------------------------------------------
__global__ __launch_bounds__(256, 4)
void capsB()
{
    __shared__ __align__(16) float wsum[2][8];

    const int tid  = threadIdx.x;
    const int b    = blockIdx.x;
    const int nb   = blockIdx.y;
    const int ns   = (nb * N_N) / NPART;
    const int ne   = ((nb + 1) * N_N) / NPART;
    const int lane = tid & 31;
    const int wid  = tid >> 5;

    // vsum for this (c, 8e), packed f32x2
    ull vs2[4];
    {
        const float4* vp = reinterpret_cast<const float4*>(
            g_vsum + (size_t)b * (N_C * N_E) + tid * 8);
        float4 v0 = vp[0], v1 = vp[1];
        vs2[0] = fpack2(v0.x, v0.y);
        vs2[1] = fpack2(v0.z, v0.w);
        vs2[2] = fpack2(v1.x, v1.y);
        vs2[3] = fpack2(v1.z, v1.w);
    }
    ull sacc2[4] = { 0ull, 0ull, 0ull, 0ull };

    // u pointer: warp reads contiguous 512B per n (perfectly coalesced)
    const uint4* __restrict__ up = reinterpret_cast<const uint4*>(
        g_u + (size_t)b * N_N * (N_C * N_E) + tid * 8);
    const int last = ne - 1;

    // register prefetch, distance 2 (row stride = U_ROW_U4 = 256 uint4)
    uint4 v0 = up[(size_t)ns * U_ROW_U4];
    uint4 v1 = up[(size_t)(ns + 1 <= last ? ns + 1 : last) * U_ROW_U4];

    for (int n = ns; n < ne; n++) {
        int npf = n + 2 <= last ? n + 2 : last;
        uint4 v2 = up[(size_t)npf * U_ROW_U4];

        // convert current tile values to packed f32x2
        ull u2[4];
        u2[0] = h2f2(v0.x);
        u2[1] = h2f2(v0.y);
        u2[2] = h2f2(v0.z);
        u2[3] = h2f2(v0.w);

        // dot(u, vsum) over this thread's 8 e (pairwise in f32x2)
        ull acc = ffma2(u2[0], vs2[0], 0ull);
        acc = ffma2(u2[1], vs2[1], acc);
        acc = ffma2(u2[2], vs2[2], acc);
        acc = ffma2(u2[3], vs2[3], acc);
        float2 af = funpack2(acc);
        float lp = af.x + af.y;
        // quad reduce -> full 32-e logit for capsule c (replicated in quad)
        lp += __shfl_xor_sync(0xffffffffu, lp, 1);
        lp += __shfl_xor_sync(0xffffffffu, lp, 2);

        float ex = __expf(lp);
        // ex is quad-replicated: xor-4/8/16 butterfly sums the 8 DISTINCT c
        float s = ex;
        s += __shfl_xor_sync(0xffffffffu, s, 4);
        s += __shfl_xor_sync(0xffffffffu, s, 8);
        s += __shfl_xor_sync(0xffffffffu, s, 16);
        if (lane == 0) wsum[n & 1][wid] = s;
        __syncthreads();

        // total over 8 warps = softmax denominator over all 64 c
        const float4* wp = reinterpret_cast<const float4*>(wsum[n & 1]);
        float4 wa = wp[0], wb = wp[1];
        float tot = ((wa.x + wa.y) + (wa.z + wa.w)) +
                    ((wb.x + wb.y) + (wb.z + wb.w));
        float coup = __fdividef(ex, tot);

        // s += coup * u  (packed)
        ull coup2 = fpack2(coup, coup);
        sacc2[0] = ffma2(coup2, u2[0], sacc2[0]);
        sacc2[1] = ffma2(coup2, u2[1], sacc2[1]);
        sacc2[2] = ffma2(coup2, u2[2], sacc2[2]);
        sacc2[3] = ffma2(coup2, u2[3], sacc2[3]);

        v0 = v1; v1 = v2;
    }

    // write partials (32B contiguous per thread)
    ull* dst = reinterpret_cast<ull*>(
        &g_partials[(size_t)nb * SBCE + (size_t)b * (N_C * N_E) + tid * 8]);
    *reinterpret_cast<ulonglong2*>(dst)     = make_ulonglong2(sacc2[0], sacc2[1]);
    *reinterpret_cast<ulonglong2*>(dst + 2) = make_ulonglong2(sacc2[2], sacc2[3]);
}

// ---------------------------------------------------------------------------
// reduce partials (round-5 proven version): 2048 blocks x 32 threads
// ---------------------------------------------------------------------------
__global__ void reduce_squash(float scale, int overwrite, float* __restrict__ out)
{
    int bc = blockIdx.x;     // b*64 + c
    int e  = threadIdx.x;
    size_t idx = (size_t)bc * N_E + e;
    float s = 0.0f;
    #pragma unroll
    for (int p = 0; p < NPART; p++)
        s += g_partials[(size_t)p * SBCE + idx];
    s *= scale;
    float nsq = s * s;
    #pragma unroll
    for (int m = 16; m >= 1; m >>= 1)
        nsq += __shfl_xor_sync(0xffffffffu, nsq, m);
    float sc = nsq / ((1.0f + nsq) * sqrtf(nsq + 1e-9f));
    float v = sc * s;
    if (overwrite) g_vsum[idx] = v;
    else           g_vsum[idx] += v;
    if (out) out[idx] = v;
}

// ---------------------------------------------------------------------------
extern "C" void kernel_launch(void* const* d_in, const int* in_sizes, int n_in,
                              void* d_out, int out_size)
{
    const float* x  = (const float*)d_in[0];
    const float* W  = (const float*)d_in[1];
    const float* Bv = (const float*)d_in[2];
    float* out = (float*)d_out;

    cudaFuncSetAttribute(capsA, cudaFuncAttributeMaxDynamicSharedMemorySize,
                         CAPSA_SMEM_BYTES);

    dim3 gA(8, NPART);
    dim3 gB(N_B, NPART);

    dumk<<<1, 32>>>();   // keeps ncu -s 5 capture on capsB (pass 3)

    capsA<<<gA, 256, CAPSA_SMEM_BYTES>>>(x, W, Bv);
    reduce_squash<<<N_B * N_C, 32>>>(1.0f / 64.0f, 1, nullptr);   // v1 -> vsum
    capsB<<<gB, 256>>>();
    reduce_squash<<<N_B * N_C, 32>>>(1.0f, 0, nullptr);           // vsum += v2
    capsB<<<gB, 256>>>();
    reduce_squash<<<N_B * N_C, 32>>>(1.0f, 0, out);
}

// round 14
// speedup vs baseline: 1.1684x; 1.0143x over previous
// CapsuleLayer r13 — capsB occupancy push: launch_bounds(256,5), padded g_u,
// clamp-free prefetch.  capsA unchanged (at DRAM roofline).
#include <cuda_runtime.h>
#include <cuda_fp16.h>

#define N_B 32
#define N_N 2048
#define N_D 16
#define N_C 64
#define N_E 32
#define NPART 37
#define SBCE (N_B * N_C * N_E)   // 65536
#define U_ROW_U4 ((N_C * N_E) / 8)   // one n-row of u in uint4 units = 256

typedef unsigned long long ull;

// Scratch (device globals; allocation-free kernel_launch)
// +2 rows padding so capsB tail prefetch (distance 2) never reads OOB.
__device__ __half g_u[(size_t)N_B * N_N * N_C * N_E + 2 * N_C * N_E];
__device__ float  g_partials[(size_t)NPART * SBCE];          // partial s sums
__device__ float  g_vsum[SBCE];                              // sum of v_j so far

// ---- packed f32x2 helpers (sm_100+) ----
__device__ __forceinline__ ull ffma2(ull a, ull b, ull c) {
    ull d;
    asm("fma.rn.f32x2 %0, %1, %2, %3;" : "=l"(d) : "l"(a), "l"(b), "l"(c));
    return d;
}
__device__ __forceinline__ ull fadd2(ull a, ull b) {
    ull d;
    asm("add.rn.f32x2 %0, %1, %2;" : "=l"(d) : "l"(a), "l"(b));
    return d;
}
__device__ __forceinline__ ull fpack2(float lo, float hi) {
    ull d;
    asm("mov.b64 %0, {%1, %2};" : "=l"(d) : "f"(lo), "f"(hi));
    return d;
}
__device__ __forceinline__ float2 funpack2(ull v) {
    float2 f;
    asm("mov.b64 {%0, %1}, %2;" : "=f"(f.x), "=f"(f.y) : "l"(v));
    return f;
}
// half2 (as u32) -> packed f32x2 (as ull)
__device__ __forceinline__ ull h2f2(unsigned h) {
    __half2 hh = reinterpret_cast<__half2&>(h);
    float2 f = __half22float2(hh);
    ull r;
    asm("mov.b64 %0, {%1, %2};" : "=l"(r) : "f"(f.x), "f"(f.y));
    return r;
}

// ---- cp.async helpers (capsA only) ----
__device__ __forceinline__ void cp16(void* smem_dst, const void* gmem_src) {
    unsigned s = (unsigned)__cvta_generic_to_shared(smem_dst);
    asm volatile("cp.async.cg.shared.global [%0], [%1], 16;" :: "r"(s), "l"(gmem_src));
}
__device__ __forceinline__ void cp_commit() {
    asm volatile("cp.async.commit_group;");
}
__device__ __forceinline__ void cp_wait3() {
    asm volatile("cp.async.wait_group 3;" ::: "memory");
}

// capsA dynamic smem: 4-deep ring.  Ws[4][4096] floats + xs[4][512] floats
#define CAPSA_WS_FLOATS (4 * 4096)
#define CAPSA_XS_FLOATS (4 * 512)
#define CAPSA_SMEM_BYTES ((CAPSA_WS_FLOATS + CAPSA_XS_FLOATS) * 4)

__global__ void dumk() {}   // 1 pad launch: aligns ncu -s 5 onto capsB pass 3

// ---------------------------------------------------------------------------
// Kernel A (unchanged — measured at its DRAM roofline, ~96us):
// u = x*W + B via packed f32x2 FFMA, store u fp16, accumulate sum_n u
// ---------------------------------------------------------------------------
__global__ __launch_bounds__(256, 2)
void capsA(const float* __restrict__ x, const float* __restrict__ W,
           const float* __restrict__ Bv)
{
    extern __shared__ float smem[];
    float* Wsm = smem;                        // [4][4096]
    float* xsm = smem + CAPSA_WS_FLOATS;      // [4][512]

    const int tid = threadIdx.x;
    const int cc  = blockIdx.x;
    const int nb  = blockIdx.y;
    const int c0  = cc * 8;
    const int ns  = (nb * N_N) / NPART;
    const int ne  = ((nb + 1) * N_N) / NPART;

    const int lane    = tid & 31;
    const int bq      = tid >> 5;
    const int c_local = lane >> 2;
    const int a       = lane & 3;
    const int swz4    = c_local & 7;
    const int c       = c0 + c_local;
    const int e_base  = 8 * a;

    ull Bv2[4];
    #pragma unroll
    for (int j = 0; j < 4; j++)
        Bv2[j] = fpack2(Bv[c * N_E + e_base + 2 * j],
                        Bv[c * N_E + e_base + 2 * j + 1]);

    ull sacc[4][4];
    #pragma unroll
    for (int i = 0; i < 4; i++)
        #pragma unroll
        for (int j = 0; j < 4; j++) sacc[i][j] = 0ull;

    auto stage = [&](int n, int buf) {
        const float* Wn = W + (size_t)n * (N_C * N_D * N_E) + (size_t)c0 * (N_D * N_E);
        float* Wb = Wsm + buf * 4096;
        #pragma unroll
        for (int k = 0; k < 4; k++) {
            int q = tid + 256 * k;
            int p = q * 4;
            int cl = p >> 9;
            int d  = (p >> 5) & 15;
            int e4 = (p & 31) >> 2;
            float* dst = &Wb[cl * 512 + d * 32 + ((e4 ^ (cl & 7)) << 2)];
            cp16(dst, Wn + p);
        }
        if (tid < 128) {
            int b = tid >> 2, dq = tid & 3;
            cp16(&xsm[buf * 512 + b * N_D + dq * 4],
                 x + ((size_t)b * N_N + n) * N_D + dq * 4);
        }
        cp_commit();
    };

    stage(ns, 0);
    if (ns + 1 < ne) stage(ns + 1, 1); else cp_commit();
    if (ns + 2 < ne) stage(ns + 2, 2); else cp_commit();

    for (int n = ns; n < ne; n++) {
        int r   = n - ns;
        int buf = r & 3;
        int nxt = n + 3;
        if (nxt < ne) stage(nxt, (r + 3) & 3); else cp_commit();
        cp_wait3();
        __syncthreads();

        ull uacc[4][4];
        #pragma unroll
        for (int i = 0; i < 4; i++)
            #pragma unroll
            for (int j = 0; j < 4; j++) uacc[i][j] = 0ull;

        const float* Wrow = Wsm + buf * 4096 + c_local * 512;
        const float* xrow = xsm + buf * 512;
        #pragma unroll
        for (int d = 0; d < N_D; d++) {
            ull xv[4];
            #pragma unroll
            for (int i = 0; i < 4; i++) {
                float xval = xrow[(bq * 4 + i) * N_D + d];
                xv[i] = fpack2(xval, xval);
            }
            int o0 = (((2 * a + 0) ^ swz4) << 2) + d * 32;
            int o1 = (((2 * a + 1) ^ swz4) << 2) + d * 32;
            ulonglong2 w01 = *reinterpret_cast<const ulonglong2*>(Wrow + o0);
            ulonglong2 w23 = *reinterpret_cast<const ulonglong2*>(Wrow + o1);
            ull wv[4] = { w01.x, w01.y, w23.x, w23.y };
            #pragma unroll
            for (int i = 0; i < 4; i++)
                #pragma unroll
                for (int j = 0; j < 4; j++)
                    uacc[i][j] = ffma2(xv[i], wv[j], uacc[i][j]);
        }

        #pragma unroll
        for (int i = 0; i < 4; i++) {
            int b = bq * 4 + i;
            unsigned h[4];
            #pragma unroll
            for (int j = 0; j < 4; j++) {
                ull t = fadd2(uacc[i][j], Bv2[j]);
                sacc[i][j] = fadd2(sacc[i][j], t);
                float2 tf = funpack2(t);
                __half2 hh = __floats2half2_rn(tf.x, tf.y);
                h[j] = reinterpret_cast<unsigned&>(hh);
            }
            size_t uoff = (((size_t)b * N_N + n) * N_C + c) * N_E + e_base;
            *reinterpret_cast<uint4*>(&g_u[uoff]) = make_uint4(h[0], h[1], h[2], h[3]);
        }
        __syncthreads();
    }

    #pragma unroll
    for (int i = 0; i < 4; i++) {
        int b = bq * 4 + i;
        ull* dst = reinterpret_cast<ull*>(
            &g_partials[(size_t)nb * SBCE + ((size_t)b * N_C + c) * N_E + e_base]);
        *reinterpret_cast<ulonglong2*>(dst)     = make_ulonglong2(sacc[i][0], sacc[i][1]);
        *reinterpret_cast<ulonglong2*>(dst + 2) = make_ulonglong2(sacc[i][2], sacc[i][3]);
    }
}

// ---------------------------------------------------------------------------
// Kernel B: logits = u.vsum, softmax_c, s += coup*u.
// Direct LDG.128, register prefetch distance 2 (clamp-free: g_u padded),
// f32x2 dot/accumulate, 3-shfl exp-sum, 1 barrier per n.
// launch_bounds(256,5): 51-reg cap -> 40 warps/SM (was 32).
// ---------------------------------------------------------------------------
__global__ __launch_bounds__(256, 5)
void capsB()
{
    __shared__ __align__(16) float wsum[2][8];

    const int tid  = threadIdx.x;
    const int b    = blockIdx.x;
    const int nb   = blockIdx.y;
    const int ns   = (nb * N_N) / NPART;
    const int ne   = ((nb + 1) * N_N) / NPART;
    const int lane = tid & 31;
    const int wid  = tid >> 5;

    // vsum for this (c, 8e), packed f32x2
    ull vs2[4];
    {
        const float4* vp = reinterpret_cast<const float4*>(
            g_vsum + (size_t)b * (N_C * N_E) + tid * 8);
        float4 v0 = vp[0], v1 = vp[1];
        vs2[0] = fpack2(v0.x, v0.y);
        vs2[1] = fpack2(v0.z, v0.w);
        vs2[2] = fpack2(v1.x, v1.y);
        vs2[3] = fpack2(v1.z, v1.w);
    }
    ull sacc2[4] = { 0ull, 0ull, 0ull, 0ull };

    // u pointer: warp reads contiguous 512B per n (perfectly coalesced)
    const uint4* __restrict__ up = reinterpret_cast<const uint4*>(
        g_u + (size_t)b * N_N * (N_C * N_E) + tid * 8);

    // register prefetch, distance 2 (tail reads padded rows; never consumed)
    uint4 v0 = up[(size_t)ns * U_ROW_U4];
    uint4 v1 = up[(size_t)(ns + 1) * U_ROW_U4];

    for (int n = ns; n < ne; n++) {
        uint4 v2 = up[(size_t)(n + 2) * U_ROW_U4];

        // convert current tile values to packed f32x2
        ull u2[4];
        u2[0] = h2f2(v0.x);
        u2[1] = h2f2(v0.y);
        u2[2] = h2f2(v0.z);
        u2[3] = h2f2(v0.w);

        // dot(u, vsum) over this thread's 8 e (pairwise in f32x2)
        ull acc = ffma2(u2[0], vs2[0], 0ull);
        acc = ffma2(u2[1], vs2[1], acc);
        acc = ffma2(u2[2], vs2[2], acc);
        acc = ffma2(u2[3], vs2[3], acc);
        float2 af = funpack2(acc);
        float lp = af.x + af.y;
        // quad reduce -> full 32-e logit for capsule c (replicated in quad)
        lp += __shfl_xor_sync(0xffffffffu, lp, 1);
        lp += __shfl_xor_sync(0xffffffffu, lp, 2);

        float ex = __expf(lp);
        // ex is quad-replicated: xor-4/8/16 butterfly sums the 8 DISTINCT c
        float s = ex;
        s += __shfl_xor_sync(0xffffffffu, s, 4);
        s += __shfl_xor_sync(0xffffffffu, s, 8);
        s += __shfl_xor_sync(0xffffffffu, s, 16);
        if (lane == 0) wsum[n & 1][wid] = s;
        __syncthreads();

        // total over 8 warps = softmax denominator over all 64 c
        const float4* wp = reinterpret_cast<const float4*>(wsum[n & 1]);
        float4 wa = wp[0], wb = wp[1];
        float tot = ((wa.x + wa.y) + (wa.z + wa.w)) +
                    ((wb.x + wb.y) + (wb.z + wb.w));
        float coup = __fdividef(ex, tot);

        // s += coup * u  (packed)
        ull coup2 = fpack2(coup, coup);
        sacc2[0] = ffma2(coup2, u2[0], sacc2[0]);
        sacc2[1] = ffma2(coup2, u2[1], sacc2[1]);
        sacc2[2] = ffma2(coup2, u2[2], sacc2[2]);
        sacc2[3] = ffma2(coup2, u2[3], sacc2[3]);

        v0 = v1; v1 = v2;
    }

    // write partials (32B contiguous per thread)
    ull* dst = reinterpret_cast<ull*>(
        &g_partials[(size_t)nb * SBCE + (size_t)b * (N_C * N_E) + tid * 8]);
    *reinterpret_cast<ulonglong2*>(dst)     = make_ulonglong2(sacc2[0], sacc2[1]);
    *reinterpret_cast<ulonglong2*>(dst + 2) = make_ulonglong2(sacc2[2], sacc2[3]);
}

// ---------------------------------------------------------------------------
// reduce partials (round-5 proven version): 2048 blocks x 32 threads
// ---------------------------------------------------------------------------
__global__ void reduce_squash(float scale, int overwrite, float* __restrict__ out)
{
    int bc = blockIdx.x;     // b*64 + c
    int e  = threadIdx.x;
    size_t idx = (size_t)bc * N_E + e;
    float s = 0.0f;
    #pragma unroll
    for (int p = 0; p < NPART; p++)
        s += g_partials[(size_t)p * SBCE + idx];
    s *= scale;
    float nsq = s * s;
    #pragma unroll
    for (int m = 16; m >= 1; m >>= 1)
        nsq += __shfl_xor_sync(0xffffffffu, nsq, m);
    float sc = nsq / ((1.0f + nsq) * sqrtf(nsq + 1e-9f));
    float v = sc * s;
    if (overwrite) g_vsum[idx] = v;
    else           g_vsum[idx] += v;
    if (out) out[idx] = v;
}

// ---------------------------------------------------------------------------
extern "C" void kernel_launch(void* const* d_in, const int* in_sizes, int n_in,
                              void* d_out, int out_size)
{
    const float* x  = (const float*)d_in[0];
    const float* W  = (const float*)d_in[1];
    const float* Bv = (const float*)d_in[2];
    float* out = (float*)d_out;

    cudaFuncSetAttribute(capsA, cudaFuncAttributeMaxDynamicSharedMemorySize,
                         CAPSA_SMEM_BYTES);

    dim3 gA(8, NPART);
    dim3 gB(N_B, NPART);

    dumk<<<1, 32>>>();   // keeps ncu -s 5 capture on capsB (pass 3)

    capsA<<<gA, 256, CAPSA_SMEM_BYTES>>>(x, W, Bv);
    reduce_squash<<<N_B * N_C, 32>>>(1.0f / 64.0f, 1, nullptr);   // v1 -> vsum
    capsB<<<gB, 256>>>();
    reduce_squash<<<N_B * N_C, 32>>>(1.0f, 0, nullptr);           // vsum += v2
    capsB<<<gB, 256>>>();
    reduce_squash<<<N_B * N_C, 32>>>(1.0f, 0, out);
}

// round 15
// speedup vs baseline: 1.2082x; 1.0341x over previous
// CapsuleLayer r15 — capsB unroll-2 (2 n per barrier, parity wsum), dumk dropped.
#include <cuda_runtime.h>
#include <cuda_fp16.h>

#define N_B 32
#define N_N 2048
#define N_D 16
#define N_C 64
#define N_E 32
#define NPART 37
#define SBCE (N_B * N_C * N_E)   // 65536
#define U_ROW_U4 ((N_C * N_E) / 8)   // one n-row of u in uint4 units = 256

typedef unsigned long long ull;

// Scratch (device globals; allocation-free kernel_launch)
// +4 rows padding: capsB pair-prefetch can touch rows ne..ne+1 past the last slab.
__device__ __half g_u[(size_t)N_B * N_N * N_C * N_E + 4 * N_C * N_E];
__device__ float  g_partials[(size_t)NPART * SBCE];          // partial s sums
__device__ float  g_vsum[SBCE];                              // sum of v_j so far

// ---- packed f32x2 helpers (sm_100+) ----
__device__ __forceinline__ ull ffma2(ull a, ull b, ull c) {
    ull d;
    asm("fma.rn.f32x2 %0, %1, %2, %3;" : "=l"(d) : "l"(a), "l"(b), "l"(c));
    return d;
}
__device__ __forceinline__ ull fadd2(ull a, ull b) {
    ull d;
    asm("add.rn.f32x2 %0, %1, %2;" : "=l"(d) : "l"(a), "l"(b));
    return d;
}
__device__ __forceinline__ ull fpack2(float lo, float hi) {
    ull d;
    asm("mov.b64 %0, {%1, %2};" : "=l"(d) : "f"(lo), "f"(hi));
    return d;
}
__device__ __forceinline__ float2 funpack2(ull v) {
    float2 f;
    asm("mov.b64 {%0, %1}, %2;" : "=f"(f.x), "=f"(f.y) : "l"(v));
    return f;
}
// half2 (as u32) -> packed f32x2 (as ull)
__device__ __forceinline__ ull h2f2(unsigned h) {
    __half2 hh = reinterpret_cast<__half2&>(h);
    float2 f = __half22float2(hh);
    ull r;
    asm("mov.b64 %0, {%1, %2};" : "=l"(r) : "f"(f.x), "f"(f.y));
    return r;
}

// ---- cp.async helpers (capsA only) ----
__device__ __forceinline__ void cp16(void* smem_dst, const void* gmem_src) {
    unsigned s = (unsigned)__cvta_generic_to_shared(smem_dst);
    asm volatile("cp.async.cg.shared.global [%0], [%1], 16;" :: "r"(s), "l"(gmem_src));
}
__device__ __forceinline__ void cp_commit() {
    asm volatile("cp.async.commit_group;");
}
__device__ __forceinline__ void cp_wait3() {
    asm volatile("cp.async.wait_group 3;" ::: "memory");
}

// capsA dynamic smem: 4-deep ring.  Ws[4][4096] floats + xs[4][512] floats
#define CAPSA_WS_FLOATS (4 * 4096)
#define CAPSA_XS_FLOATS (4 * 512)
#define CAPSA_SMEM_BYTES ((CAPSA_WS_FLOATS + CAPSA_XS_FLOATS) * 4)

// ---------------------------------------------------------------------------
// Kernel A (unchanged — measured at its DRAM roofline, ~96us):
// u = x*W + B via packed f32x2 FFMA, store u fp16, accumulate sum_n u
// ---------------------------------------------------------------------------
__global__ __launch_bounds__(256, 2)
void capsA(const float* __restrict__ x, const float* __restrict__ W,
           const float* __restrict__ Bv)
{
    extern __shared__ float smem[];
    float* Wsm = smem;                        // [4][4096]
    float* xsm = smem + CAPSA_WS_FLOATS;      // [4][512]

    const int tid = threadIdx.x;
    const int cc  = blockIdx.x;
    const int nb  = blockIdx.y;
    const int c0  = cc * 8;
    const int ns  = (nb * N_N) / NPART;
    const int ne  = ((nb + 1) * N_N) / NPART;

    const int lane    = tid & 31;
    const int bq      = tid >> 5;
    const int c_local = lane >> 2;
    const int a       = lane & 3;
    const int swz4    = c_local & 7;
    const int c       = c0 + c_local;
    const int e_base  = 8 * a;

    ull Bv2[4];
    #pragma unroll
    for (int j = 0; j < 4; j++)
        Bv2[j] = fpack2(Bv[c * N_E + e_base + 2 * j],
                        Bv[c * N_E + e_base + 2 * j + 1]);

    ull sacc[4][4];
    #pragma unroll
    for (int i = 0; i < 4; i++)
        #pragma unroll
        for (int j = 0; j < 4; j++) sacc[i][j] = 0ull;

    auto stage = [&](int n, int buf) {
        const float* Wn = W + (size_t)n * (N_C * N_D * N_E) + (size_t)c0 * (N_D * N_E);
        float* Wb = Wsm + buf * 4096;
        #pragma unroll
        for (int k = 0; k < 4; k++) {
            int q = tid + 256 * k;
            int p = q * 4;
            int cl = p >> 9;
            int d  = (p >> 5) & 15;
            int e4 = (p & 31) >> 2;
            float* dst = &Wb[cl * 512 + d * 32 + ((e4 ^ (cl & 7)) << 2)];
            cp16(dst, Wn + p);
        }
        if (tid < 128) {
            int b = tid >> 2, dq = tid & 3;
            cp16(&xsm[buf * 512 + b * N_D + dq * 4],
                 x + ((size_t)b * N_N + n) * N_D + dq * 4);
        }
        cp_commit();
    };

    stage(ns, 0);
    if (ns + 1 < ne) stage(ns + 1, 1); else cp_commit();
    if (ns + 2 < ne) stage(ns + 2, 2); else cp_commit();

    for (int n = ns; n < ne; n++) {
        int r   = n - ns;
        int buf = r & 3;
        int nxt = n + 3;
        if (nxt < ne) stage(nxt, (r + 3) & 3); else cp_commit();
        cp_wait3();
        __syncthreads();

        ull uacc[4][4];
        #pragma unroll
        for (int i = 0; i < 4; i++)
            #pragma unroll
            for (int j = 0; j < 4; j++) uacc[i][j] = 0ull;

        const float* Wrow = Wsm + buf * 4096 + c_local * 512;
        const float* xrow = xsm + buf * 512;
        #pragma unroll
        for (int d = 0; d < N_D; d++) {
            ull xv[4];
            #pragma unroll
            for (int i = 0; i < 4; i++) {
                float xval = xrow[(bq * 4 + i) * N_D + d];
                xv[i] = fpack2(xval, xval);
            }
            int o0 = (((2 * a + 0) ^ swz4) << 2) + d * 32;
            int o1 = (((2 * a + 1) ^ swz4) << 2) + d * 32;
            ulonglong2 w01 = *reinterpret_cast<const ulonglong2*>(Wrow + o0);
            ulonglong2 w23 = *reinterpret_cast<const ulonglong2*>(Wrow + o1);
            ull wv[4] = { w01.x, w01.y, w23.x, w23.y };
            #pragma unroll
            for (int i = 0; i < 4; i++)
                #pragma unroll
                for (int j = 0; j < 4; j++)
                    uacc[i][j] = ffma2(xv[i], wv[j], uacc[i][j]);
        }

        #pragma unroll
        for (int i = 0; i < 4; i++) {
            int b = bq * 4 + i;
            unsigned h[4];
            #pragma unroll
            for (int j = 0; j < 4; j++) {
                ull t = fadd2(uacc[i][j], Bv2[j]);
                sacc[i][j] = fadd2(sacc[i][j], t);
                float2 tf = funpack2(t);
                __half2 hh = __floats2half2_rn(tf.x, tf.y);
                h[j] = reinterpret_cast<unsigned&>(hh);
            }
            size_t uoff = (((size_t)b * N_N + n) * N_C + c) * N_E + e_base;
            *reinterpret_cast<uint4*>(&g_u[uoff]) = make_uint4(h[0], h[1], h[2], h[3]);
        }
        __syncthreads();
    }

    #pragma unroll
    for (int i = 0; i < 4; i++) {
        int b = bq * 4 + i;
        ull* dst = reinterpret_cast<ull*>(
            &g_partials[(size_t)nb * SBCE + ((size_t)b * N_C + c) * N_E + e_base]);
        *reinterpret_cast<ulonglong2*>(dst)     = make_ulonglong2(sacc[i][0], sacc[i][1]);
        *reinterpret_cast<ulonglong2*>(dst + 2) = make_ulonglong2(sacc[i][2], sacc[i][3]);
    }
}

// ---------------------------------------------------------------------------
// Kernel B: logits = u.vsum, softmax_c, s += coup*u.
// Unroll-2: two independent n processed per barrier (halves barrier count,
// doubles ILP on the shfl/exp chain).  Parity wsum[2][2][8] keeps one-barrier
// -per-pair hazard-free.  Direct LDG.128, pair-prefetch distance 1.
// ---------------------------------------------------------------------------
__global__ __launch_bounds__(256, 4)
void capsB()
{
    __shared__ __align__(16) float wsum[2][2][8];   // [parity][which n][warp]

    const int tid  = threadIdx.x;
    const int b    = blockIdx.x;
    const int nb   = blockIdx.y;
    const int ns   = (nb * N_N) / NPART;
    const int ne   = ((nb + 1) * N_N) / NPART;
    const int lane = tid & 31;
    const int wid  = tid >> 5;

    // vsum for this (c, 8e), packed f32x2
    ull vs2[4];
    {
        const float4* vp = reinterpret_cast<const float4*>(
            g_vsum + (size_t)b * (N_C * N_E) + tid * 8);
        float4 v0 = vp[0], v1 = vp[1];
        vs2[0] = fpack2(v0.x, v0.y);
        vs2[1] = fpack2(v0.z, v0.w);
        vs2[2] = fpack2(v1.x, v1.y);
        vs2[3] = fpack2(v1.z, v1.w);
    }
    ull sacc2[4] = { 0ull, 0ull, 0ull, 0ull };

    const uint4* __restrict__ up = reinterpret_cast<const uint4*>(
        g_u + (size_t)b * N_N * (N_C * N_E) + tid * 8);

    const int cnt    = ne - ns;          // 55 or 56
    const int npairs = cnt >> 1;

    uint4 v0 = up[(size_t)ns * U_ROW_U4];
    uint4 v1 = up[(size_t)(ns + 1) * U_ROW_U4];

    int p = 0;
    int n = ns;
    for (int it = 0; it < npairs; it++, n += 2, p ^= 1) {
        uint4 v2 = up[(size_t)(n + 2) * U_ROW_U4];   // next pair (padded tail)
        uint4 v3 = up[(size_t)(n + 3) * U_ROW_U4];

        ull a0 = h2f2(v0.x), a1 = h2f2(v0.y), a2 = h2f2(v0.z), a3 = h2f2(v0.w);
        ull b0 = h2f2(v1.x), b1 = h2f2(v1.y), b2 = h2f2(v1.z), b3 = h2f2(v1.w);

        ull accA = ffma2(a0, vs2[0], 0ull);
        ull accB = ffma2(b0, vs2[0], 0ull);
        accA = ffma2(a1, vs2[1], accA);
        accB = ffma2(b1, vs2[1], accB);
        accA = ffma2(a2, vs2[2], accA);
        accB = ffma2(b2, vs2[2], accB);
        accA = ffma2(a3, vs2[3], accA);
        accB = ffma2(b3, vs2[3], accB);
        float2 fA = funpack2(accA);
        float2 fB = funpack2(accB);
        float lpA = fA.x + fA.y;
        float lpB = fB.x + fB.y;
        lpA += __shfl_xor_sync(0xffffffffu, lpA, 1);
        lpB += __shfl_xor_sync(0xffffffffu, lpB, 1);
        lpA += __shfl_xor_sync(0xffffffffu, lpA, 2);
        lpB += __shfl_xor_sync(0xffffffffu, lpB, 2);

        float exA = __expf(lpA);
        float exB = __expf(lpB);
        float sA = exA, sB = exB;
        sA += __shfl_xor_sync(0xffffffffu, sA, 4);
        sB += __shfl_xor_sync(0xffffffffu, sB, 4);
        sA += __shfl_xor_sync(0xffffffffu, sA, 8);
        sB += __shfl_xor_sync(0xffffffffu, sB, 8);
        sA += __shfl_xor_sync(0xffffffffu, sA, 16);
        sB += __shfl_xor_sync(0xffffffffu, sB, 16);
        if (lane == 0) {
            wsum[p][0][wid] = sA;
            wsum[p][1][wid] = sB;
        }
        __syncthreads();

        const float4* wpA = reinterpret_cast<const float4*>(wsum[p][0]);
        const float4* wpB = reinterpret_cast<const float4*>(wsum[p][1]);
        float4 aA = wpA[0], bA = wpA[1];
        float4 aB = wpB[0], bB = wpB[1];
        float totA = ((aA.x + aA.y) + (aA.z + aA.w)) +
                     ((bA.x + bA.y) + (bA.z + bA.w));
        float totB = ((aB.x + aB.y) + (aB.z + aB.w)) +
                     ((bB.x + bB.y) + (bB.z + bB.w));
        float coupA = __fdividef(exA, totA);
        float coupB = __fdividef(exB, totB);

        ull cA = fpack2(coupA, coupA);
        ull cB = fpack2(coupB, coupB);
        sacc2[0] = ffma2(cA, a0, sacc2[0]);
        sacc2[1] = ffma2(cA, a1, sacc2[1]);
        sacc2[2] = ffma2(cA, a2, sacc2[2]);
        sacc2[3] = ffma2(cA, a3, sacc2[3]);
        sacc2[0] = ffma2(cB, b0, sacc2[0]);
        sacc2[1] = ffma2(cB, b1, sacc2[1]);
        sacc2[2] = ffma2(cB, b2, sacc2[2]);
        sacc2[3] = ffma2(cB, b3, sacc2[3]);

        v0 = v2; v1 = v3;
    }

    if (cnt & 1) {
        // tail n = ns + cnt - 1; its row already sits in v0
        ull a0 = h2f2(v0.x), a1 = h2f2(v0.y), a2 = h2f2(v0.z), a3 = h2f2(v0.w);
        ull acc = ffma2(a0, vs2[0], 0ull);
        acc = ffma2(a1, vs2[1], acc);
        acc = ffma2(a2, vs2[2], acc);
        acc = ffma2(a3, vs2[3], acc);
        float2 f = funpack2(acc);
        float lp = f.x + f.y;
        lp += __shfl_xor_sync(0xffffffffu, lp, 1);
        lp += __shfl_xor_sync(0xffffffffu, lp, 2);
        float ex = __expf(lp);
        float s = ex;
        s += __shfl_xor_sync(0xffffffffu, s, 4);
        s += __shfl_xor_sync(0xffffffffu, s, 8);
        s += __shfl_xor_sync(0xffffffffu, s, 16);
        if (lane == 0) wsum[p][0][wid] = s;
        __syncthreads();
        const float4* wp = reinterpret_cast<const float4*>(wsum[p][0]);
        float4 wa = wp[0], wb = wp[1];
        float tot = ((wa.x + wa.y) + (wa.z + wa.w)) +
                    ((wb.x + wb.y) + (wb.z + wb.w));
        float coup = __fdividef(ex, tot);
        ull c2 = fpack2(coup, coup);
        sacc2[0] = ffma2(c2, a0, sacc2[0]);
        sacc2[1] = ffma2(c2, a1, sacc2[1]);
        sacc2[2] = ffma2(c2, a2, sacc2[2]);
        sacc2[3] = ffma2(c2, a3, sacc2[3]);
    }

    // write partials (32B contiguous per thread)
    ull* dst = reinterpret_cast<ull*>(
        &g_partials[(size_t)nb * SBCE + (size_t)b * (N_C * N_E) + tid * 8]);
    *reinterpret_cast<ulonglong2*>(dst)     = make_ulonglong2(sacc2[0], sacc2[1]);
    *reinterpret_cast<ulonglong2*>(dst + 2) = make_ulonglong2(sacc2[2], sacc2[3]);
}

// ---------------------------------------------------------------------------
// reduce partials (round-5 proven version): 2048 blocks x 32 threads
// ---------------------------------------------------------------------------
__global__ void reduce_squash(float scale, int overwrite, float* __restrict__ out)
{
    int bc = blockIdx.x;     // b*64 + c
    int e  = threadIdx.x;
    size_t idx = (size_t)bc * N_E + e;
    float s = 0.0f;
    #pragma unroll
    for (int p = 0; p < NPART; p++)
        s += g_partials[(size_t)p * SBCE + idx];
    s *= scale;
    float nsq = s * s;
    #pragma unroll
    for (int m = 16; m >= 1; m >>= 1)
        nsq += __shfl_xor_sync(0xffffffffu, nsq, m);
    float sc = nsq / ((1.0f + nsq) * sqrtf(nsq + 1e-9f));
    float v = sc * s;
    if (overwrite) g_vsum[idx] = v;
    else           g_vsum[idx] += v;
    if (out) out[idx] = v;
}

// ---------------------------------------------------------------------------
extern "C" void kernel_launch(void* const* d_in, const int* in_sizes, int n_in,
                              void* d_out, int out_size)
{
    const float* x  = (const float*)d_in[0];
    const float* W  = (const float*)d_in[1];
    const float* Bv = (const float*)d_in[2];
    float* out = (float*)d_out;

    cudaFuncSetAttribute(capsA, cudaFuncAttributeMaxDynamicSharedMemorySize,
                         CAPSA_SMEM_BYTES);

    dim3 gA(8, NPART);
    dim3 gB(N_B, NPART);

    capsA<<<gA, 256, CAPSA_SMEM_BYTES>>>(x, W, Bv);
    reduce_squash<<<N_B * N_C, 32>>>(1.0f / 64.0f, 1, nullptr);   // v1 -> vsum
    capsB<<<gB, 256>>>();
    reduce_squash<<<N_B * N_C, 32>>>(1.0f, 0, nullptr);           // vsum += v2
    capsB<<<gB, 256>>>();
    reduce_squash<<<N_B * N_C, 32>>>(1.0f, 0, out);
}